// round 7
// baseline (speedup 1.0000x reference)
#include <cuda_runtime.h>
#include <cuda_fp16.h>
#include <cstdint>

typedef unsigned long long ull;

// Problem shape (fixed by the dataset)
#define NN 50000     // nodes
#define KK 256       // in feats
#define MM 128       // out feats
#define EE 800000    // edges

#define SCAN_B 512
#define NB_SCAN ((NN + SCAN_B - 1) / SCAN_B)   // 98

// Static scratch (no allocs allowed). Zero-initialized at load; reduce_kernel
// restores g_cnt to zero each launch, so the hist invariant holds every call.
__device__ __half g_hw[(size_t)NN * MM];  // h @ W in fp16 (12.8 MB, L2-resident)
__device__ int   g_cnt[NN];               // degree histogram (zero at entry)
__device__ int   g_off[NN];               // CSR exclusive offsets
__device__ int   g_pos[NN];               // fill cursors
__device__ int   g_bsum[NB_SCAN + 32];    // scan block sums
__device__ int   g_srcs[EE];              // src ids grouped by dst

// ---------------------------------------------------------------------------
// Kernel 1: hw = h @ W via mma.sync m16n8k8 tf32 (single-pass tf32 W).
//
// CTA: 256 rows x 128 cols, 8 warps x 32 rows (2 m16 row-groups per warp).
// SMEM:
//   hs[256][68]  fp32(tf32-bits) h chunk; A-frag bank = 4*l4 + q -> conflict-free
//   Wk[8][512]   float2 lane-ordered B fragments for ONE K-chunk (restaged x4):
//     Wk[ks*512 + nt*32 + lane] = ( tf32 W[kc*64+ks*8+q][nt*8+l4],
//                                   tf32 W[kc*64+ks*8+q+4][nt*8+l4] )
//     (q = lane&3, l4 = lane>>2)
//     -> one coalesced, conflict-free LDS.64 per (nt) yields BOTH B regs,
//        shared by the warp's 2 row-group MMAs.
// ---------------------------------------------------------------------------
#define HS_PAD 68
#define HS_FLOATS (256 * HS_PAD)                    // 17408 floats = 69632 B
#define GEMM_SMEM (HS_FLOATS * 4 + 8 * 512 * 8)     // 69632 + 32768 = 102400 B

__device__ __forceinline__ unsigned f2tf32(float x) {
    unsigned r;
    asm("cvt.rna.tf32.f32 %0, %1;" : "=r"(r) : "f"(x));
    return r;
}

__global__ __launch_bounds__(256)
void gemm_kernel(const float* __restrict__ h, const float* __restrict__ W) {
    extern __shared__ float smem[];
    float*  hs = smem;                          // [256][HS_PAD]
    float2* Wk = (float2*)(smem + HS_FLOATS);   // [8][512]

    const int tid  = threadIdx.x;
    const int warp = tid >> 5;
    const int lane = tid & 31;
    const int q    = lane & 3;    // k-offset within frag
    const int l4   = lane >> 2;   // row/col group

    const int blk_row0 = blockIdx.x * 256;

    float d[2][16][4];
    #pragma unroll
    for (int g = 0; g < 2; g++)
        #pragma unroll
        for (int nt = 0; nt < 16; nt++)
            #pragma unroll
            for (int j = 0; j < 4; j++) d[g][nt][j] = 0.f;

    for (int kc = 0; kc < 4; kc++) {            // 4 chunks of K=64
        if (kc) __syncthreads();                // drain readers before restage

        // stage B fragments for this K-chunk (layout mirrors consumer exactly)
        for (int idx = tid; idx < 8 * 512; idx += 256) {
            const int ks = idx >> 9;            // 0..7
            const int r  = idx & 511;
            const int nt = r >> 5;              // 0..15
            const int le = r & 31;
            const int lq  = le & 3;
            const int ll4 = le >> 2;
            const int col = nt * 8 + ll4;
            const int k0  = kc * 64 + ks * 8 + lq;
            Wk[idx] = make_float2(
                __uint_as_float(f2tf32(W[k0 * MM + col])),
                __uint_as_float(f2tf32(W[(k0 + 4) * MM + col])));
        }
        // stage h chunk: 256 rows x 64 cols, tf32-converted
        for (int i = tid; i < 256 * 16; i += 256) {
            const int row = i >> 4;
            const int f4  = i & 15;
            int rg = blk_row0 + row;
            if (rg >= NN) rg = NN - 1;
            float4 v = __ldg((const float4*)(h + (size_t)rg * KK + kc * 64) + f4);
            v.x = __uint_as_float(f2tf32(v.x));
            v.y = __uint_as_float(f2tf32(v.y));
            v.z = __uint_as_float(f2tf32(v.z));
            v.w = __uint_as_float(f2tf32(v.w));
            ((float4*)(hs + row * HS_PAD))[f4] = v;
        }
        __syncthreads();

        #pragma unroll
        for (int ks = 0; ks < 8; ks++) {        // 8 k-steps of 8
            const int k8 = ks * 8;
            unsigned a[2][4];
            #pragma unroll
            for (int g = 0; g < 2; g++) {
                const int ar = warp * 32 + g * 16 + l4;
                a[g][0] = __float_as_uint(hs[(ar    ) * HS_PAD + k8 + q    ]);
                a[g][1] = __float_as_uint(hs[(ar + 8) * HS_PAD + k8 + q    ]);
                a[g][2] = __float_as_uint(hs[(ar    ) * HS_PAD + k8 + q + 4]);
                a[g][3] = __float_as_uint(hs[(ar + 8) * HS_PAD + k8 + q + 4]);
            }
            const float2* wrow = Wk + ks * 512;

            #pragma unroll
            for (int nt = 0; nt < 16; nt++) {
                const float2 bb = wrow[nt * 32 + lane];   // coalesced LDS.64
                const unsigned b0 = __float_as_uint(bb.x);
                const unsigned b1 = __float_as_uint(bb.y);
                #pragma unroll
                for (int g = 0; g < 2; g++) {
                    asm("mma.sync.aligned.m16n8k8.row.col.f32.tf32.tf32.f32 "
                        "{%0,%1,%2,%3}, {%4,%5,%6,%7}, {%8,%9}, {%0,%1,%2,%3};"
                        : "+f"(d[g][nt][0]), "+f"(d[g][nt][1]),
                          "+f"(d[g][nt][2]), "+f"(d[g][nt][3])
                        : "r"(a[g][0]), "r"(a[g][1]), "r"(a[g][2]), "r"(a[g][3]),
                          "r"(b0), "r"(b1));
                }
            }
        }
    }

    // epilogue: fp16 store. d0,d1 at (l4, 2q..2q+1), d2,d3 at (l4+8, ..)
    #pragma unroll
    for (int g = 0; g < 2; g++) {
        const int r0 = blk_row0 + warp * 32 + g * 16 + l4;
        #pragma unroll
        for (int nt = 0; nt < 16; nt++) {
            const int col = nt * 8 + q * 2;
            if (r0 < NN)
                *(__half2*)(g_hw + (size_t)r0 * MM + col) =
                    __floats2half2_rn(d[g][nt][0], d[g][nt][1]);
            if (r0 + 8 < NN)
                *(__half2*)(g_hw + (size_t)(r0 + 8) * MM + col) =
                    __floats2half2_rn(d[g][nt][2], d[g][nt][3]);
        }
    }
}

// ---------------------------------------------------------------------------
// CSR build kernels (g_cnt arrives zeroed: initial static init + reduce_kernel)
// ---------------------------------------------------------------------------
__global__ void hist_kernel(const int* __restrict__ dst, int E) {
    int e = blockIdx.x * blockDim.x + threadIdx.x;
    if (e < E) atomicAdd(&g_cnt[dst[e]], 1);
}

// warp-shuffle exclusive scan of 512 counts per block; write block total
__global__ __launch_bounds__(SCAN_B)
void scan1_kernel() {
    __shared__ int wsum[16];
    const int t = threadIdx.x;
    const int lane = t & 31;
    const int warp = t >> 5;
    const int i = blockIdx.x * SCAN_B + t;
    const int v = (i < NN) ? g_cnt[i] : 0;

    int x = v;
    #pragma unroll
    for (int off = 1; off < 32; off <<= 1) {
        int y = __shfl_up_sync(0xffffffffu, x, off);
        if (lane >= off) x += y;
    }
    if (lane == 31) wsum[warp] = x;
    __syncthreads();
    if (warp == 0 && lane < 16) {
        int w = wsum[lane];
        int xw = w;
        #pragma unroll
        for (int off = 1; off < 16; off <<= 1) {
            int y = __shfl_up_sync(0xffffu, xw, off);
            if (lane >= off) xw += y;
        }
        wsum[lane] = xw - w;
    }
    __syncthreads();
    const int base = wsum[warp];
    if (i < NN) g_off[i] = base + x - v;
    if (t == SCAN_B - 1) g_bsum[blockIdx.x] = base + x;
}

// exclusive scan of NB_SCAN (=98) block sums
__global__ __launch_bounds__(128)
void scan2_kernel() {
    __shared__ int wsum[4];
    const int t = threadIdx.x;
    const int lane = t & 31;
    const int warp = t >> 5;
    const int v = (t < NB_SCAN) ? g_bsum[t] : 0;

    int x = v;
    #pragma unroll
    for (int off = 1; off < 32; off <<= 1) {
        int y = __shfl_up_sync(0xffffffffu, x, off);
        if (lane >= off) x += y;
    }
    if (lane == 31) wsum[warp] = x;
    __syncthreads();
    if (warp == 0 && lane < 4) {
        int w = wsum[lane];
        int xw = w;
        #pragma unroll
        for (int off = 1; off < 4; off <<= 1) {
            int y = __shfl_up_sync(0xfu, xw, off);
            if (lane >= off) xw += y;
        }
        wsum[lane] = xw - w;
    }
    __syncthreads();
    if (t < NB_SCAN) g_bsum[t] = wsum[warp] + x - v;
}

// add block offsets; init fill cursors
__global__ void scan3_kernel() {
    int i = blockIdx.x * blockDim.x + threadIdx.x;
    if (i < NN) {
        int o = g_off[i] + g_bsum[i >> 9];
        g_off[i] = o;
        g_pos[i] = o;
    }
}

__global__ void fill_kernel(const int* __restrict__ src, const int* __restrict__ dst, int E) {
    int e = blockIdx.x * blockDim.x + threadIdx.x;
    if (e < E) {
        int p = atomicAdd(&g_pos[dst[e]], 1);
        g_srcs[p] = src[e];
    }
}

// ---------------------------------------------------------------------------
// Segmented reduce: one warp per node; fp16 gather, fp32 accumulate;
// fused bias + relu epilogue. Zeroes g_cnt[n] for the next launch.
// ---------------------------------------------------------------------------
__global__ __launch_bounds__(256)
void reduce_kernel(const float* __restrict__ b, float* __restrict__ out) {
    const int n = (int)((blockIdx.x * (unsigned)blockDim.x + threadIdx.x) >> 5);
    if (n >= NN) return;
    const int lane = threadIdx.x & 31;

    const int beg = g_off[n];
    const int deg = g_cnt[n];
    if (lane == 0) g_cnt[n] = 0;   // restore invariant for next launch

    float4 acc = make_float4(0.f, 0.f, 0.f, 0.f);

    int i = 0;
    for (; i + 4 <= deg; i += 4) {
        const int s0 = __ldg(&g_srcs[beg + i]);
        const int s1 = __ldg(&g_srcs[beg + i + 1]);
        const int s2 = __ldg(&g_srcs[beg + i + 2]);
        const int s3 = __ldg(&g_srcs[beg + i + 3]);
        const uint2 v0 = __ldg((const uint2*)(g_hw + (size_t)s0 * MM) + lane);
        const uint2 v1 = __ldg((const uint2*)(g_hw + (size_t)s1 * MM) + lane);
        const uint2 v2 = __ldg((const uint2*)(g_hw + (size_t)s2 * MM) + lane);
        const uint2 v3 = __ldg((const uint2*)(g_hw + (size_t)s3 * MM) + lane);
        #pragma unroll
        for (int j = 0; j < 4; j++) {
            const uint2 vv = (j == 0) ? v0 : (j == 1) ? v1 : (j == 2) ? v2 : v3;
            const float2 p0 = __half22float2(*(const __half2*)&vv.x);
            const float2 p1 = __half22float2(*(const __half2*)&vv.y);
            acc.x += p0.x; acc.y += p0.y; acc.z += p1.x; acc.w += p1.y;
        }
    }
    for (; i < deg; i++) {
        const int s0 = __ldg(&g_srcs[beg + i]);
        const uint2 v0 = __ldg((const uint2*)(g_hw + (size_t)s0 * MM) + lane);
        const float2 p0 = __half22float2(*(const __half2*)&v0.x);
        const float2 p1 = __half22float2(*(const __half2*)&v0.y);
        acc.x += p0.x; acc.y += p0.y; acc.z += p1.x; acc.w += p1.y;
    }

    const float4 bv = __ldg((const float4*)b + lane);
    acc.x = fmaxf(acc.x + bv.x, 0.f);
    acc.y = fmaxf(acc.y + bv.y, 0.f);
    acc.z = fmaxf(acc.z + bv.z, 0.f);
    acc.w = fmaxf(acc.w + bv.w, 0.f);

    ((float4*)(out + (size_t)n * MM))[lane] = acc;
}

// ---------------------------------------------------------------------------
// Launch: h, W, b, src, dst  ->  out [N, 128] fp32
// ---------------------------------------------------------------------------
extern "C" void kernel_launch(void* const* d_in, const int* in_sizes, int n_in,
                              void* d_out, int out_size) {
    const float* h = (const float*)d_in[0];
    const float* W = (const float*)d_in[1];
    const float* b = (const float*)d_in[2];
    const int* src = (const int*)d_in[3];
    const int* dst = (const int*)d_in[4];
    float* out = (float*)d_out;

    const int E = in_sizes[3];

    static bool attr_set = false;
    if (!attr_set) {
        cudaFuncSetAttribute(gemm_kernel,
                             cudaFuncAttributeMaxDynamicSharedMemorySize,
                             GEMM_SMEM);
        attr_set = true;
    }

    // 1) hw = h @ W (tensor cores, fp16 out)
    gemm_kernel<<<(NN + 255) / 256, 256, GEMM_SMEM>>>(h, W);

    // 2) CSR build (g_cnt is zero on entry — see reduce_kernel)
    hist_kernel<<<(E + 255) / 256, 256>>>(dst, E);
    scan1_kernel<<<NB_SCAN, SCAN_B>>>();
    scan2_kernel<<<1, 128>>>();
    scan3_kernel<<<(NN + 255) / 256, 256>>>();
    fill_kernel<<<(E + 255) / 256, 256>>>(src, dst, E);

    // 3) segmented reduce + bias + relu (one warp per node)
    {
        const long long threads = (long long)NN * 32;
        reduce_kernel<<<(int)((threads + 255) / 256), 256>>>(b, out);
    }
}

// round 8
// speedup vs baseline: 1.1336x; 1.1336x over previous
#include <cuda_runtime.h>
#include <cuda_fp16.h>
#include <cstdint>

typedef unsigned long long ull;

// Problem shape (fixed by the dataset)
#define NN 50000     // nodes
#define KK 256       // in feats
#define MM 128       // out feats
#define EE 800000    // edges

#define SCAN_B 512
#define NB_SCAN ((NN + SCAN_B - 1) / SCAN_B)   // 98

// Static scratch (no allocs allowed). Zero-initialized at load; reduce_kernel
// restores g_cnt to zero each launch, so the hist invariant holds every call.
__device__ __half g_hw[(size_t)NN * MM];  // h @ W in fp16 (12.8 MB, L2-resident)
__device__ int   g_cnt[NN];               // degree histogram (zero at entry)
__device__ int   g_off[NN];               // CSR exclusive offsets
__device__ int   g_pos[NN];               // fill cursors
__device__ int   g_bsum[NB_SCAN + 32];    // scan block sums
__device__ int   g_srcs[EE];              // src ids grouped by dst
// Lane-ordered tf32 B-fragment table, built once per launch by wfrag_kernel:
//   g_wfrag[kg*512 + nt*32 + le] = ( tf32 W[kg*8 + (le&3)][nt*8 + (le>>2)],
//                                    tf32 W[kg*8 + (le&3) + 4][nt*8 + (le>>2)] )
// float4-aligned so GEMM can copy it with coalesced float4 ops.
__device__ float4 g_wfrag4[32 * 512 / 2];        // 128 KB

__device__ __forceinline__ unsigned f2tf32(float x) {
    unsigned r;
    asm("cvt.rna.tf32.f32 %0, %1;" : "=r"(r) : "f"(x));
    return r;
}

// ---------------------------------------------------------------------------
// Kernel 0: build lane-ordered B-fragment table (one entry per thread)
// ---------------------------------------------------------------------------
__global__ __launch_bounds__(256)
void wfrag_kernel(const float* __restrict__ W) {
    const int idx = blockIdx.x * 256 + threadIdx.x;   // 0 .. 16383
    if (idx >= 32 * 512) return;
    const int kg = idx >> 9;          // k-step group 0..31
    const int r  = idx & 511;
    const int nt = r >> 5;            // 0..15
    const int le = r & 31;
    const int lq  = le & 3;
    const int ll4 = le >> 2;
    const int col = nt * 8 + ll4;
    const int k0  = kg * 8 + lq;
    float2* out = (float2*)g_wfrag4;
    out[idx] = make_float2(
        __uint_as_float(f2tf32(W[k0 * MM + col])),
        __uint_as_float(f2tf32(W[(k0 + 4) * MM + col])));
}

// ---------------------------------------------------------------------------
// Kernel 1: hw = h @ W via mma.sync m16n8k8 tf32 (single-pass tf32 W).
//
// CTA: 64 rows x 128 cols, 128 threads = 4 warps x 16 rows (one m16 group).
// smem 50176 B -> 4 CTAs/SM; 64 accum regs/thread.
//   hs[64][68]  tf32-bit h chunk; A-frag banks = 4*l4 + q -> conflict-free
//   Wk[8][512]  per-chunk B fragments, copied coalesced from g_wfrag4
// ---------------------------------------------------------------------------
#define HS_PAD 68
#define HS_FLOATS (64 * HS_PAD)                     // 4352 floats = 17408 B
#define GEMM_SMEM (HS_FLOATS * 4 + 8 * 512 * 8)     // 17408 + 32768 = 50176 B

__global__ __launch_bounds__(128, 4)
void gemm_kernel(const float* __restrict__ h) {
    extern __shared__ float smem[];
    float*  hs  = smem;                          // [64][HS_PAD]
    float2* Wk  = (float2*)(smem + HS_FLOATS);   // [8][512]
    float4* Wk4 = (float4*)Wk;

    const int tid  = threadIdx.x;
    const int warp = tid >> 5;
    const int lane = tid & 31;
    const int q    = lane & 3;    // k-offset within frag
    const int l4   = lane >> 2;   // row/col group

    const int blk_row0 = blockIdx.x * 64;

    float d[16][4];
    #pragma unroll
    for (int nt = 0; nt < 16; nt++)
        #pragma unroll
        for (int j = 0; j < 4; j++) d[nt][j] = 0.f;

    for (int kc = 0; kc < 4; kc++) {            // 4 chunks of K=64
        if (kc) __syncthreads();                // drain readers before restage

        // stage B fragments: coalesced float4 copy (2048 float4, 16/thread)
        {
            const float4* src = g_wfrag4 + kc * (8 * 512 / 2);
            #pragma unroll
            for (int i = 0; i < 16; i++)
                Wk4[tid + i * 128] = __ldg(src + tid + i * 128);
        }
        // stage h chunk: 64 rows x 64 cols, tf32-converted (1024 float4, 8/thread)
        #pragma unroll
        for (int i = 0; i < 8; i++) {
            const int e   = tid + i * 128;      // 0..1023
            const int row = e >> 4;
            const int f4  = e & 15;
            int rg = blk_row0 + row;
            if (rg >= NN) rg = NN - 1;
            float4 v = __ldg((const float4*)(h + (size_t)rg * KK + kc * 64) + f4);
            v.x = __uint_as_float(f2tf32(v.x));
            v.y = __uint_as_float(f2tf32(v.y));
            v.z = __uint_as_float(f2tf32(v.z));
            v.w = __uint_as_float(f2tf32(v.w));
            ((float4*)(hs + row * HS_PAD))[f4] = v;
        }
        __syncthreads();

        #pragma unroll
        for (int ks = 0; ks < 8; ks++) {        // 8 k-steps of 8
            const int k8 = ks * 8;
            const int ar = warp * 16 + l4;
            const unsigned a0 = __float_as_uint(hs[(ar    ) * HS_PAD + k8 + q    ]);
            const unsigned a1 = __float_as_uint(hs[(ar + 8) * HS_PAD + k8 + q    ]);
            const unsigned a2 = __float_as_uint(hs[(ar    ) * HS_PAD + k8 + q + 4]);
            const unsigned a3 = __float_as_uint(hs[(ar + 8) * HS_PAD + k8 + q + 4]);
            const float2* wrow = Wk + ks * 512;

            #pragma unroll
            for (int nt = 0; nt < 16; nt++) {
                const float2 bb = wrow[nt * 32 + lane];   // coalesced LDS.64
                asm("mma.sync.aligned.m16n8k8.row.col.f32.tf32.tf32.f32 "
                    "{%0,%1,%2,%3}, {%4,%5,%6,%7}, {%8,%9}, {%0,%1,%2,%3};"
                    : "+f"(d[nt][0]), "+f"(d[nt][1]),
                      "+f"(d[nt][2]), "+f"(d[nt][3])
                    : "r"(a0), "r"(a1), "r"(a2), "r"(a3),
                      "r"(__float_as_uint(bb.x)), "r"(__float_as_uint(bb.y)));
            }
        }
    }

    // epilogue: fp16 store. d0,d1 at (l4, 2q..2q+1), d2,d3 at (l4+8, ..)
    const int r0 = blk_row0 + warp * 16 + l4;
    #pragma unroll
    for (int nt = 0; nt < 16; nt++) {
        const int col = nt * 8 + q * 2;
        if (r0 < NN)
            *(__half2*)(g_hw + (size_t)r0 * MM + col) =
                __floats2half2_rn(d[nt][0], d[nt][1]);
        if (r0 + 8 < NN)
            *(__half2*)(g_hw + (size_t)(r0 + 8) * MM + col) =
                __floats2half2_rn(d[nt][2], d[nt][3]);
    }
}

// ---------------------------------------------------------------------------
// CSR build kernels (g_cnt arrives zeroed: initial static init + reduce_kernel)
// ---------------------------------------------------------------------------
__global__ void hist_kernel(const int* __restrict__ dst, int E) {
    int e = blockIdx.x * blockDim.x + threadIdx.x;
    if (e < E) atomicAdd(&g_cnt[dst[e]], 1);
}

// warp-shuffle exclusive scan of 512 counts per block; write block total
__global__ __launch_bounds__(SCAN_B)
void scan1_kernel() {
    __shared__ int wsum[16];
    const int t = threadIdx.x;
    const int lane = t & 31;
    const int warp = t >> 5;
    const int i = blockIdx.x * SCAN_B + t;
    const int v = (i < NN) ? g_cnt[i] : 0;

    int x = v;
    #pragma unroll
    for (int off = 1; off < 32; off <<= 1) {
        int y = __shfl_up_sync(0xffffffffu, x, off);
        if (lane >= off) x += y;
    }
    if (lane == 31) wsum[warp] = x;
    __syncthreads();
    if (warp == 0 && lane < 16) {
        int w = wsum[lane];
        int xw = w;
        #pragma unroll
        for (int off = 1; off < 16; off <<= 1) {
            int y = __shfl_up_sync(0xffffu, xw, off);
            if (lane >= off) xw += y;
        }
        wsum[lane] = xw - w;
    }
    __syncthreads();
    const int base = wsum[warp];
    if (i < NN) g_off[i] = base + x - v;
    if (t == SCAN_B - 1) g_bsum[blockIdx.x] = base + x;
}

// exclusive scan of NB_SCAN (=98) block sums
__global__ __launch_bounds__(128)
void scan2_kernel() {
    __shared__ int wsum[4];
    const int t = threadIdx.x;
    const int lane = t & 31;
    const int warp = t >> 5;
    const int v = (t < NB_SCAN) ? g_bsum[t] : 0;

    int x = v;
    #pragma unroll
    for (int off = 1; off < 32; off <<= 1) {
        int y = __shfl_up_sync(0xffffffffu, x, off);
        if (lane >= off) x += y;
    }
    if (lane == 31) wsum[warp] = x;
    __syncthreads();
    if (warp == 0 && lane < 4) {
        int w = wsum[lane];
        int xw = w;
        #pragma unroll
        for (int off = 1; off < 4; off <<= 1) {
            int y = __shfl_up_sync(0xfu, xw, off);
            if (lane >= off) xw += y;
        }
        wsum[lane] = xw - w;
    }
    __syncthreads();
    if (t < NB_SCAN) g_bsum[t] = wsum[warp] + x - v;
}

// add block offsets; init fill cursors
__global__ void scan3_kernel() {
    int i = blockIdx.x * blockDim.x + threadIdx.x;
    if (i < NN) {
        int o = g_off[i] + g_bsum[i >> 9];
        g_off[i] = o;
        g_pos[i] = o;
    }
}

__global__ void fill_kernel(const int* __restrict__ src, const int* __restrict__ dst, int E) {
    int e = blockIdx.x * blockDim.x + threadIdx.x;
    if (e < E) {
        int p = atomicAdd(&g_pos[dst[e]], 1);
        g_srcs[p] = src[e];
    }
}

// ---------------------------------------------------------------------------
// Segmented reduce: one warp per node; fp16 gather, fp32 accumulate;
// fused bias + relu epilogue. Zeroes g_cnt[n] for the next launch.
// ---------------------------------------------------------------------------
__global__ __launch_bounds__(256)
void reduce_kernel(const float* __restrict__ b, float* __restrict__ out) {
    const int n = (int)((blockIdx.x * (unsigned)blockDim.x + threadIdx.x) >> 5);
    if (n >= NN) return;
    const int lane = threadIdx.x & 31;

    const int beg = g_off[n];
    const int deg = g_cnt[n];
    if (lane == 0) g_cnt[n] = 0;   // restore invariant for next launch

    float4 acc = make_float4(0.f, 0.f, 0.f, 0.f);

    int i = 0;
    for (; i + 4 <= deg; i += 4) {
        const int s0 = __ldg(&g_srcs[beg + i]);
        const int s1 = __ldg(&g_srcs[beg + i + 1]);
        const int s2 = __ldg(&g_srcs[beg + i + 2]);
        const int s3 = __ldg(&g_srcs[beg + i + 3]);
        const uint2 v0 = __ldg((const uint2*)(g_hw + (size_t)s0 * MM) + lane);
        const uint2 v1 = __ldg((const uint2*)(g_hw + (size_t)s1 * MM) + lane);
        const uint2 v2 = __ldg((const uint2*)(g_hw + (size_t)s2 * MM) + lane);
        const uint2 v3 = __ldg((const uint2*)(g_hw + (size_t)s3 * MM) + lane);
        #pragma unroll
        for (int j = 0; j < 4; j++) {
            const uint2 vv = (j == 0) ? v0 : (j == 1) ? v1 : (j == 2) ? v2 : v3;
            const float2 p0 = __half22float2(*(const __half2*)&vv.x);
            const float2 p1 = __half22float2(*(const __half2*)&vv.y);
            acc.x += p0.x; acc.y += p0.y; acc.z += p1.x; acc.w += p1.y;
        }
    }
    for (; i < deg; i++) {
        const int s0 = __ldg(&g_srcs[beg + i]);
        const uint2 v0 = __ldg((const uint2*)(g_hw + (size_t)s0 * MM) + lane);
        const float2 p0 = __half22float2(*(const __half2*)&v0.x);
        const float2 p1 = __half22float2(*(const __half2*)&v0.y);
        acc.x += p0.x; acc.y += p0.y; acc.z += p1.x; acc.w += p1.y;
    }

    const float4 bv = __ldg((const float4*)b + lane);
    acc.x = fmaxf(acc.x + bv.x, 0.f);
    acc.y = fmaxf(acc.y + bv.y, 0.f);
    acc.z = fmaxf(acc.z + bv.z, 0.f);
    acc.w = fmaxf(acc.w + bv.w, 0.f);

    ((float4*)(out + (size_t)n * MM))[lane] = acc;
}

// ---------------------------------------------------------------------------
// Launch: h, W, b, src, dst  ->  out [N, 128] fp32
// ---------------------------------------------------------------------------
extern "C" void kernel_launch(void* const* d_in, const int* in_sizes, int n_in,
                              void* d_out, int out_size) {
    const float* h = (const float*)d_in[0];
    const float* W = (const float*)d_in[1];
    const float* b = (const float*)d_in[2];
    const int* src = (const int*)d_in[3];
    const int* dst = (const int*)d_in[4];
    float* out = (float*)d_out;

    const int E = in_sizes[3];

    static bool attr_set = false;
    if (!attr_set) {
        cudaFuncSetAttribute(gemm_kernel,
                             cudaFuncAttributeMaxDynamicSharedMemorySize,
                             GEMM_SMEM);
        attr_set = true;
    }

    // 0) build lane-ordered tf32 B-fragment table (16384 entries)
    wfrag_kernel<<<64, 256>>>(W);

    // 1) hw = h @ W (tensor cores, fp16 out)
    gemm_kernel<<<(NN + 63) / 64, 128, GEMM_SMEM>>>(h);

    // 2) CSR build (g_cnt is zero on entry — see reduce_kernel)
    hist_kernel<<<(E + 255) / 256, 256>>>(dst, E);
    scan1_kernel<<<NB_SCAN, SCAN_B>>>();
    scan2_kernel<<<1, 128>>>();
    scan3_kernel<<<(NN + 255) / 256, 256>>>();
    fill_kernel<<<(E + 255) / 256, 256>>>(src, dst, E);

    // 3) segmented reduce + bias + relu (one warp per node)
    {
        const long long threads = (long long)NN * 32;
        reduce_kernel<<<(int)((threads + 255) / 256), 256>>>(b, out);
    }
}